// round 14
// baseline (speedup 1.0000x reference)
#include <cuda_runtime.h>

// out[i] = sum_b sum_j x1[b,j] * x2[b,(i-j) mod 1024]
// R14: four-step shuffle FFT (1024 = 32x32), 1024 threads/CTA, ONE FFT
// instance per thread (instance = warp id). Minimal per-thread critical path,
// 32 warps/SM. 5 CTA barriers + one ticket barrier + distributed reduction.

#define BSZ 128
#define D   1024
#define PAD 33

__device__ float    g_partial[BSZ * D];
__device__ unsigned g_counter = 0;

__device__ __forceinline__ float2 cmul(float2 a, float2 w) {
    return make_float2(a.x * w.x - a.y * w.y, a.x * w.y + a.y * w.x);
}
__device__ __forceinline__ float2 cmulc(float2 a, float2 w) {   // a * conj(w)
    return make_float2(a.x * w.x + a.y * w.y, a.y * w.x - a.x * w.y);
}
__device__ __forceinline__ float2 cadd(float2 a, float2 b) { return make_float2(a.x + b.x, a.y + b.y); }
__device__ __forceinline__ float2 csub(float2 a, float2 b) { return make_float2(a.x - b.x, a.y - b.y); }

__device__ __forceinline__ float2 shflx(float2 v, int h) {
    return make_float2(__shfl_xor_sync(0xFFFFFFFFu, v.x, h),
                       __shfl_xor_sync(0xFFFFFFFFu, v.y, h));
}

// e^{sign * 2*pi*i*m/1024}
__device__ __forceinline__ float2 tw1024(int m, float sign) {
    const int mm = (m >= 512) ? m - 1024 : m;
    float s, c;
    __sincosf(sign * 0.006135923151542565f * (float)mm, &s, &c);
    return make_float2(c, s);
}

// 5-stage 32-pt DIF FFT across lanes, single instance.
// Input natural order (lane = index); output: lane l holds result[rev5(l)].
template <bool INV>
__device__ __forceinline__ float2 fft32(float2 V, const float2 tw[5], int lane) {
    #pragma unroll
    for (int s = 0; s < 5; s++) {
        const int  h  = 16 >> s;
        const bool up = (lane & h) != 0;
        const float2 p   = shflx(V, h);
        const float2 sum = cadd(p, V);
        const float2 dif = csub(p, V);
        const float2 m   = INV ? cmulc(dif, tw[s]) : cmul(dif, tw[s]);
        V = up ? m : sum;
    }
    return V;
}

// Spectrum unpack + pointwise product: P[k] from Z[k], Z[(D-k)%D].
__device__ __forceinline__ float2 spec_prod(float2 zk, float2 zm) {
    const float a = zk.x, bb = zk.y, c = zm.x, d = zm.y;
    const float x1r = a + c,  x1i = bb - d;
    const float x2r = bb + d, x2i = c - a;
    return make_float2(0.25f * (x1r * x2r - x1i * x2i),
                       0.25f * (x1r * x2i + x1i * x2r));
}

__global__ void __launch_bounds__(1024, 1)
fftconv8_kernel(const float* __restrict__ x1, const float* __restrict__ x2,
                float* __restrict__ out) {
    __shared__ float2 sA[PAD * 32];
    __shared__ float2 sB[PAD * 32];
    __shared__ float  sR[PAD * 32];
    __shared__ float  red[1024];

    const int tid  = threadIdx.x;
    const int lane = tid & 31;
    const int w    = tid >> 5;      // warp 0..31 = FFT instance id
    const int b    = blockIdx.x;

    // ---- issue global loads FIRST (coalesced) ----
    const float a0 = x1[b * D + tid];
    const float c0 = x2[b * D + tid];

    // ---- per-lane stage twiddles: tw[s] = e^{-2pi*i*((lane&(h-1))<<s)/32} ----
    float2 tw[5];
    #pragma unroll
    for (int s = 0; s < 5; s++) {
        const int h = 16 >> s;
        const int m = (lane & (h - 1)) << s;
        float sn, cs;
        __sincosf(-0.19634954084936207f * (float)m, &sn, &cs);  // -2*pi/32
        tw[s] = make_float2(cs, sn);
    }
    const int rv = (int)(__brev((unsigned)lane) >> 27);  // rev5(lane)

    // ---- pack z = x1 + i*x2 into sA[n] at 33*(n>>5) + (n&31) ----
    sA[PAD * w + lane] = make_float2(a0, c0);
    __syncthreads();

    float2 V;

    // ---- fwd inner: FFT over a-index (lane), instance col = w ----
    V = sA[PAD * lane + w];
    V = fft32<false>(V, tw, lane);
    // lane holds A[c][w], c = rv. Twiddle e^{-2pi*i*w*c/1024}, transpose-store.
    V = cmul(V, tw1024(w * rv, -1.0f));
    sB[PAD * rv + w] = V;
    __syncthreads();

    // ---- fwd outer: FFT over b-index (lane), instance c = w ----
    V = sB[PAD * w + lane];
    V = fft32<false>(V, tw, lane);
    // lane holds Z[c + 32*d], d = rv. Store spectrum at sA[33*c + d].
    sA[PAD * w + rv] = V;
    __syncthreads();

    // ---- product + inv inner: instance c = w, lane = d ----
    {
        const float2 zk = sA[PAD * w + lane];
        const int c2 = (32 - w) & 31;
        const int d2 = (w == 0) ? ((32 - lane) & 31) : (31 - lane);
        const float2 zm = sA[PAD * c2 + d2];
        V = spec_prod(zk, zm);
    }
    V = fft32<true>(V, tw, lane);
    // lane holds B[bcol][w], bcol = rv. Twiddle e^{+2pi*i*bcol*w/1024}, transpose.
    V = cmul(V, tw1024(rv * w, +1.0f));
    sB[PAD * rv + w] = V;
    __syncthreads();

    // ---- inv outer: instance bcol = w, lane = c ----
    V = sB[PAD * w + lane];
    V = fft32<true>(V, tw, lane);
    // lane holds y[32*a + w]*N, a = rv (real by construction)
    sR[PAD * rv + w] = V.x * (1.0f / D);
    __syncthreads();

    // ---- coalesced writeout of y_b (one float per thread) ----
    g_partial[b * D + tid] = sR[PAD * (tid >> 5) + (tid & 31)];

    // ---- single cross-CTA barrier (monotonic ticket, replay-safe) ----
    __syncthreads();
    if (tid == 0) {
        __threadfence();  // release g_partial writes
        const unsigned old    = atomicAdd(&g_counter, 1u);
        const unsigned target = old - (old & (BSZ - 1)) + BSZ;
        unsigned cur;
        do {
            asm volatile("ld.global.acquire.gpu.u32 %0, [%1];"
                         : "=r"(cur) : "l"(&g_counter));
        } while ((int)(cur - target) < 0);
    }
    __syncthreads();

    // ---- fused deterministic reduction: CTA c owns outputs [8c, 8c+8) ----
    {
        const int i    = blockIdx.x * 8 + (tid & 7);
        const int brow = tid >> 3;  // 0..127 — one load per thread
        red[tid] = __ldcg(&g_partial[brow * D + i]);
        __syncthreads();
        if (tid < 256) {
            red[tid] = red[tid] + red[tid + 256] + red[tid + 512] + red[tid + 768];
        }
        __syncthreads();
        if (tid < 8) {
            float t = 0.f;
            #pragma unroll
            for (int m = 0; m < 32; m++) t += red[tid + 8 * m];
            out[blockIdx.x * 8 + tid] = t;
        }
    }
}

extern "C" void kernel_launch(void* const* d_in, const int* in_sizes, int n_in,
                              void* d_out, int out_size) {
    const float* x1  = (const float*)d_in[0];  // (128, 1024) fp32
    const float* x2  = (const float*)d_in[1];  // (128, 1024) fp32
    float*       out = (float*)d_out;          // (1,1,1024) fp32

    fftconv8_kernel<<<BSZ, 1024>>>(x1, x2, out);
}